// round 8
// baseline (speedup 1.0000x reference)
#include <cuda_runtime.h>
#include <cuda_fp16.h>
#include <math_constants.h>
#include <cstdint>

// Shapes: latents [16,2048,512] -> [32768,512], embedding [8192,512]
constexpr int DDIM  = 512;
constexpr int KCODE = 8192;
constexpr int NROWS = 16 * 2048;

constexpr int TM = 128;
constexpr int TN = 128;
constexpr int KB = 128;          // fp8 elems per stage row = 128B
constexpr int NSTAGE = 3;
constexpr int NKS = DDIM / KB;   // 4
constexpr int NRT = NROWS / TM;  // 256
constexpr int NCT = KCODE / TN;  // 64

constexpr uint32_t STAGE_BYTES = TM * KB;                   // 16384
constexpr uint32_t B_OFF       = NSTAGE * STAGE_BYTES;      // 49152
constexpr uint32_t SMEM_BYTES  = 2 * NSTAGE * STAGE_BYTES;  // 98304

// E is pre-scaled by 8192 (exact power of two) before e4m3 quantization.
constexpr float SCORE_SCL = -2.0f / 8192.0f;   // exact in fp32

// ---------------- scratch ----------------
__device__ uint32_t g_Xb8[NROWS * DDIM / 4];   // e4m3, 4 per word
__device__ uint32_t g_Eb8[KCODE * DDIM / 4];   // e4m3 of (e * 8192)
__device__ float    g_e2[KCODE];
__device__ float    g_x2[NROWS];
__device__ __half   g_score[(size_t)NROWS * KCODE];   // 512 MB approx scores
__device__ unsigned g_rowmin[NROWS];                  // float-ordered keys

// ---------------- helpers ----------------
__device__ __forceinline__ uint32_t smem_u32(const void* p) {
    uint32_t a;
    asm("{ .reg .u64 t; cvta.to.shared.u64 t, %1; cvt.u32.u64 %0, t; }" : "=r"(a) : "l"(p));
    return a;
}
__device__ __forceinline__ unsigned fkey(float f) {          // order-preserving
    unsigned b = __float_as_uint(f);
    return b ^ (unsigned)(((int)b >> 31) | 0x80000000);
}
__device__ __forceinline__ float funkey(unsigned k) {
    unsigned b = k ^ (unsigned)((~(int)k >> 31) | 0x80000000);
    return __uint_as_float(b);
}
__device__ __forceinline__ uint32_t fp8x4(float e0, float e1, float e2, float e3) {
    uint16_t lo, hi;   // cvt d, a, b -> d[7:0]=cvt(b), d[15:8]=cvt(a)
    asm("cvt.rn.satfinite.e4m3x2.f32 %0, %1, %2;" : "=h"(lo) : "f"(e1), "f"(e0));
    asm("cvt.rn.satfinite.e4m3x2.f32 %0, %1, %2;" : "=h"(hi) : "f"(e3), "f"(e2));
    return (uint32_t)lo | ((uint32_t)hi << 16);
}
__device__ __forceinline__ void mma32(float* d, const uint32_t* a, const uint32_t* b) {
    asm volatile(
        "mma.sync.aligned.m16n8k32.row.col.f32.e4m3.e4m3.f32 "
        "{%0,%1,%2,%3}, {%4,%5,%6,%7}, {%8,%9}, {%0,%1,%2,%3};"
        : "+f"(d[0]), "+f"(d[1]), "+f"(d[2]), "+f"(d[3])
        : "r"(a[0]), "r"(a[1]), "r"(a[2]), "r"(a[3]), "r"(b[0]), "r"(b[1]));
}
#define LDSM_X4(r0, r1, r2, r3, addr)                                            \
    asm volatile("ldmatrix.sync.aligned.m8n8.x4.shared.b16 {%0,%1,%2,%3}, [%4];" \
        : "=r"(r0), "=r"(r1), "=r"(r2), "=r"(r3) : "r"(addr))
#define CP_ASYNC16(dst, src) \
    asm volatile("cp.async.cg.shared.global [%0], [%1], 16;" :: "r"(dst), "l"(src) : "memory")
#define CP_COMMIT()  asm volatile("cp.async.commit_group;" ::: "memory")
#define CP_WAIT1()   asm volatile("cp.async.wait_group 1;" ::: "memory")

// ---------------------------------------------------------------------------
// Kernel 1: norms (R1-proven structure) + e4m3 convert + rowmin init
// ---------------------------------------------------------------------------
__global__ void prep_kernel(const float* __restrict__ X, const float* __restrict__ E) {
    int w    = (blockIdx.x * blockDim.x + threadIdx.x) >> 5;
    int lane = threadIdx.x & 31;
    if (w >= KCODE + NROWS) return;
    bool isE = (w < KCODE);
    int  r   = isE ? w : (w - KCODE);
    const float4* p = (const float4*)(isE ? (E + (size_t)r * DDIM) : (X + (size_t)r * DDIM));

    float s = 0.f;
#pragma unroll
    for (int i = 0; i < 4; i++) {
        float4 v = p[lane + 32 * i];
        s += v.x * v.x + v.y * v.y + v.z * v.z + v.w * v.w;
    }
#pragma unroll
    for (int o = 16; o > 0; o >>= 1) s += __shfl_xor_sync(0xffffffffu, s, o);
    if (lane == 0) {
        if (isE) g_e2[r] = s;
        else { g_x2[r] = s; g_rowmin[r] = 0xFFFFFFFFu; }
    }

    const float scl = isE ? 8192.0f : 1.0f;
    uint32_t* dst = (isE ? g_Eb8 : g_Xb8) + (size_t)r * (DDIM / 4);
#pragma unroll
    for (int i = 0; i < 4; i++) {
        float4 v = p[lane + 32 * i];
        dst[lane + 32 * i] = fp8x4(v.x * scl, v.y * scl, v.z * scl, v.w * scl);
    }
}

// ---------------------------------------------------------------------------
// Kernel 2: e4m3 GEMM (128x128 tile, K=512) via ldmatrix + mma.sync.m16n8k32.
// Stores fp16 scores AND per-row approximate min (atomicMin on ordered keys).
// ---------------------------------------------------------------------------
__global__ __launch_bounds__(256, 2) void vq_mma_kernel() {
    extern __shared__ char smem[];
    const uint32_t sb = smem_u32(smem);
    const int tid = threadIdx.x;
    const int wid = tid >> 5, lane = tid & 31;
    const int g = lane >> 2, tig = lane & 3;
    const int wm = wid & 3, wn = wid >> 2;          // warp grid 4 x 2
    const int rt = blockIdx.x >> 6;                 // col-tile fastest (L2 reuse)
    const int ct = blockIdx.x & 63;
    const int row0 = rt * TM;
    const int col0 = ct * TN;

    // ks in fp8-elem units; row stride = 128 elems = 32 words
    auto stage_cp = [&](int s, int ks) {
#pragma unroll
        for (int i = 0; i < 4; i++) {               // A: 1024 16B chunks
            int u = tid + 256 * i, row = u >> 3, c = u & 7;
            const void* src = g_Xb8 + (size_t)(row0 + row) * (DDIM / 4) + (ks >> 2) + c * 4;
            uint32_t dst = sb + (uint32_t)s * STAGE_BYTES +
                           (uint32_t)(row * 128 + (c ^ (row & 7)) * 16);
            CP_ASYNC16(dst, src);
        }
#pragma unroll
        for (int i = 0; i < 4; i++) {               // B: 1024 16B chunks
            int u = tid + 256 * i, row = u >> 3, c = u & 7;
            const void* src = g_Eb8 + (size_t)(col0 + row) * (DDIM / 4) + (ks >> 2) + c * 4;
            uint32_t dst = sb + B_OFF + (uint32_t)s * STAGE_BYTES +
                           (uint32_t)(row * 128 + (c ^ (row & 7)) * 16);
            CP_ASYNC16(dst, src);
        }
    };

    // ldmatrix per-lane source rows (sel = which 8x8 matrix this lane feeds);
    // identical quadrant pattern to the bf16 version — fragments reinterpret
    // 16-bit elements as fp8 byte pairs, giving the e4m3 k32 layout exactly.
    const int lrow = lane & 7, sel = lane >> 3;
    int arow[2]; const int acb = sel >> 1;
#pragma unroll
    for (int mt = 0; mt < 2; mt++) arow[mt] = wm * 32 + mt * 16 + lrow + (sel & 1) * 8;
    int brow[4]; const int bcb = sel & 1;
#pragma unroll
    for (int ntp = 0; ntp < 4; ntp++) brow[ntp] = wn * 64 + ntp * 16 + (sel >> 1) * 8 + lrow;

    float acc[2][8][4];
#pragma unroll
    for (int mt = 0; mt < 2; mt++)
#pragma unroll
        for (int nt = 0; nt < 8; nt++)
#pragma unroll
            for (int q = 0; q < 4; q++) acc[mt][nt][q] = 0.f;

    stage_cp(0, 0);  CP_COMMIT();
    stage_cp(1, KB); CP_COMMIT();

    for (int ks = 0; ks < NKS; ks++) {
        CP_WAIT1();
        __syncthreads();
        if (ks < NKS - 2) stage_cp((ks + 2) % NSTAGE, (ks + 2) * KB);
        CP_COMMIT();

        const int buf = ks % NSTAGE;
        const uint32_t As = sb + (uint32_t)buf * STAGE_BYTES;
        const uint32_t Bs = sb + B_OFF + (uint32_t)buf * STAGE_BYTES;

#pragma unroll
        for (int s32 = 0; s32 < 4; s32++) {         // k32 chunk = 16B pair (2s, 2s+1)
            uint32_t a[2][4];
#pragma unroll
            for (int mt = 0; mt < 2; mt++) {
                int c = 2 * s32 + acb;
                uint32_t ad = As + arow[mt] * 128 + ((c ^ (arow[mt] & 7)) * 16);
                LDSM_X4(a[mt][0], a[mt][1], a[mt][2], a[mt][3], ad);
            }
            uint32_t b[8][2];
#pragma unroll
            for (int ntp = 0; ntp < 4; ntp++) {
                int c = 2 * s32 + bcb;
                uint32_t bd = Bs + brow[ntp] * 128 + ((c ^ (brow[ntp] & 7)) * 16);
                LDSM_X4(b[2 * ntp][0], b[2 * ntp][1], b[2 * ntp + 1][0], b[2 * ntp + 1][1], bd);
            }
#pragma unroll
            for (int nt = 0; nt < 8; nt++) {
                mma32(acc[0][nt], a[0], b[nt]);
                mma32(acc[1][nt], a[1], b[nt]);
            }
        }
    }

    // ---- epilogue: score = e2 + dot*(-2/8192) -> fp16 store + per-row min ----
#pragma unroll
    for (int mt = 0; mt < 2; mt++) {
#pragma unroll
        for (int rr = 0; rr < 2; rr++) {
            int row = row0 + wm * 32 + mt * 16 + g + rr * 8;
            __half* srow = g_score + ((size_t)row << 13);
            float rmin = CUDART_INF_F;
#pragma unroll
            for (int nt = 0; nt < 8; nt++) {
                int col = col0 + wn * 64 + nt * 8 + 2 * tig;
                float s0 = fmaf(acc[mt][nt][rr * 2],     SCORE_SCL, __ldg(&g_e2[col]));
                float s1 = fmaf(acc[mt][nt][rr * 2 + 1], SCORE_SCL, __ldg(&g_e2[col + 1]));
                rmin = fminf(rmin, fminf(s0, s1));
                *(__half2*)(srow + col) = __floats2half2_rn(s0, s1);
            }
            rmin = fminf(rmin, __shfl_xor_sync(0xffffffffu, rmin, 1));
            rmin = fminf(rmin, __shfl_xor_sync(0xffffffffu, rmin, 2));
            if (tig == 0) atomicMin(&g_rowmin[row], fkey(rmin));
        }
    }
}

// ---------------------------------------------------------------------------
// Kernel 3: single-pass rescue + fused gather/STE. One warp per row.
// Margin 3e-3: fp8 screen worst-case tail (large-deviation bound ~e^-44/row)
// + ref tie window (1.9e-4) + half store ulp. Rescue dist form is byte-
// identical to the rel_err==0.0-proven R4/R6/R7 path.
// ---------------------------------------------------------------------------
__global__ __launch_bounds__(256) void rescue_gather_kernel(
    const float* __restrict__ X, const float* __restrict__ E,
    float* __restrict__ out) {
    int w    = (blockIdx.x * blockDim.x + threadIdx.x) >> 5;
    int lane = threadIdx.x & 31;
    if (w >= NROWS) return;
    const int row = w;
    const uint4* sv = (const uint4*)(g_score + ((size_t)row << 13));
    const float Tf = funkey(g_rowmin[row]) + 3e-3f;

    const float x2v = g_x2[row];
    const float* xr = X + (size_t)row * DDIM;
    unsigned long long best = ~0ull;

    for (int it = 0; it < 32; it++) {
        uint4 v = __ldg(&sv[lane + 32 * it]);
        __half2 h0 = *(__half2*)&v.x, h1 = *(__half2*)&v.y;
        __half2 h2 = *(__half2*)&v.z, h3 = *(__half2*)&v.w;
        __half2 mn2 = __hmin2(__hmin2(h0, h1), __hmin2(h2, h3));
        float mn = fminf(__low2float(mn2), __high2float(mn2));
        if (mn <= Tf) {                               // rare: ~3-4 hits / row
            const __half2 hh[4] = {h0, h1, h2, h3};
#pragma unroll
            for (int q = 0; q < 4; q++) {
                float2 f = __half22float2(hh[q]);
                float sc2[2] = {f.x, f.y};
#pragma unroll
                for (int e = 0; e < 2; e++) {
                    if (sc2[e] <= Tf) {
                        int k = (lane + 32 * it) * 8 + q * 2 + e;
                        const float* er = E + (size_t)k * DDIM;
                        float acc = 0.f;
                        for (int d = 0; d < DDIM; d++) acc += xr[d] * er[d];
                        float t    = x2v + g_e2[k];
                        float dist = t - 2.0f * acc;   // exact R1-form dist
                        unsigned long long p =
                            ((unsigned long long)__float_as_uint(dist) << 32) | (unsigned)k;
                        best = (p < best) ? p : best;
                    }
                }
            }
        }
    }
#pragma unroll
    for (int o = 16; o > 0; o >>= 1) {
        unsigned long long q = __shfl_xor_sync(0xffffffffu, best, o);
        best = (q < best) ? q : best;
    }
    const int c = (int)(unsigned)(best & 0xffffffffull);

    // fused gather + STE rounding: out = x + (e - x)
    const float4* ep = (const float4*)(E + (size_t)c * DDIM);
    const float4* xp = (const float4*)xr;
    float4* op = (float4*)(out + (size_t)row * DDIM);
#pragma unroll
    for (int i = 0; i < 4; i++) {
        float4 e = ep[lane + 32 * i];
        float4 x = xp[lane + 32 * i];
        float4 o;
        o.x = __fadd_rn(x.x, __fsub_rn(e.x, x.x));
        o.y = __fadd_rn(x.y, __fsub_rn(e.y, x.y));
        o.z = __fadd_rn(x.z, __fsub_rn(e.z, x.z));
        o.w = __fadd_rn(x.w, __fsub_rn(e.w, x.w));
        op[lane + 32 * i] = o;
    }
}

// ---------------------------------------------------------------------------
extern "C" void kernel_launch(void* const* d_in, const int* in_sizes, int n_in,
                              void* d_out, int out_size) {
    const float* X = (const float*)d_in[0];
    const float* E = (const float*)d_in[1];
    float* out = (float*)d_out;

    cudaFuncSetAttribute(vq_mma_kernel, cudaFuncAttributeMaxDynamicSharedMemorySize,
                         SMEM_BYTES);

    int warps = KCODE + NROWS;
    prep_kernel<<<(warps * 32 + 255) / 256, 256>>>(X, E);
    vq_mma_kernel<<<NRT * NCT, 256, SMEM_BYTES>>>();
    rescue_gather_kernel<<<NROWS / 8, 256>>>(X, E, out);
}

// round 9
// speedup vs baseline: 1.9295x; 1.9295x over previous
#include <cuda_runtime.h>
#include <cuda_fp16.h>
#include <math_constants.h>
#include <cstdint>

// Shapes: latents [16,2048,512] -> [32768,512], embedding [8192,512]
constexpr int DDIM  = 512;
constexpr int KCODE = 8192;
constexpr int NROWS = 16 * 2048;

constexpr int TM = 128;
constexpr int TN = 128;
constexpr int KB = 128;          // int8 elems per stage row = 128B
constexpr int NSTAGE = 3;
constexpr int NKS = DDIM / KB;   // 4
constexpr int NRT = NROWS / TM;  // 256
constexpr int NCT = KCODE / TN;  // 64

constexpr uint32_t STAGE_BYTES = TM * KB;                   // 16384
constexpr uint32_t B_OFF       = NSTAGE * STAGE_BYTES;      // 49152
constexpr uint32_t SMEM_BYTES  = 2 * NSTAGE * STAGE_BYTES;  // 98304

// ---------------- scratch ----------------
__device__ uint32_t g_Xb8[NROWS * DDIM / 4];   // s8: round(x * 127/mx_row)
__device__ uint32_t g_Eb8[KCODE * DDIM / 4];   // s8: round(e * 8192*127)
__device__ float    g_e2[KCODE];
__device__ float    g_x2[NROWS];
__device__ float    g_fct[NROWS];              // -2*mx/(127*127*8192) per row
__device__ __half   g_score[(size_t)NROWS * KCODE];   // 512 MB approx scores
__device__ unsigned g_rowmin[NROWS];                  // float-ordered keys

// ---------------- helpers ----------------
__device__ __forceinline__ uint32_t smem_u32(const void* p) {
    uint32_t a;
    asm("{ .reg .u64 t; cvta.to.shared.u64 t, %1; cvt.u32.u64 %0, t; }" : "=r"(a) : "l"(p));
    return a;
}
__device__ __forceinline__ unsigned fkey(float f) {          // order-preserving
    unsigned b = __float_as_uint(f);
    return b ^ (unsigned)(((int)b >> 31) | 0x80000000);
}
__device__ __forceinline__ float funkey(unsigned k) {
    unsigned b = k ^ (unsigned)((~(int)k >> 31) | 0x80000000);
    return __uint_as_float(b);
}
__device__ __forceinline__ uint32_t s8x4(float a, float b, float c, float d) {
    int ia = __float2int_rn(a), ib = __float2int_rn(b);
    int ic = __float2int_rn(c), id = __float2int_rn(d);
    return (uint32_t)(ia & 0xff) | ((uint32_t)(ib & 0xff) << 8) |
           ((uint32_t)(ic & 0xff) << 16) | ((uint32_t)(id & 0xff) << 24);
}
__device__ __forceinline__ void mma32s8(int* d, const uint32_t* a, const uint32_t* b) {
    asm volatile(
        "mma.sync.aligned.m16n8k32.row.col.s32.s8.s8.s32 "
        "{%0,%1,%2,%3}, {%4,%5,%6,%7}, {%8,%9}, {%0,%1,%2,%3};"
        : "+r"(d[0]), "+r"(d[1]), "+r"(d[2]), "+r"(d[3])
        : "r"(a[0]), "r"(a[1]), "r"(a[2]), "r"(a[3]), "r"(b[0]), "r"(b[1]));
}
#define LDSM_X4(r0, r1, r2, r3, addr)                                            \
    asm volatile("ldmatrix.sync.aligned.m8n8.x4.shared.b16 {%0,%1,%2,%3}, [%4];" \
        : "=r"(r0), "=r"(r1), "=r"(r2), "=r"(r3) : "r"(addr))
#define CP_ASYNC16(dst, src) \
    asm volatile("cp.async.cg.shared.global [%0], [%1], 16;" :: "r"(dst), "l"(src) : "memory")
#define CP_COMMIT()  asm volatile("cp.async.commit_group;" ::: "memory")
#define CP_WAIT1()   asm volatile("cp.async.wait_group 1;" ::: "memory")

// ---------------------------------------------------------------------------
// Kernel 1: norms + per-row max (warp reduces) + s8 quantize + rowmin init
// ---------------------------------------------------------------------------
__global__ void prep_kernel(const float* __restrict__ X, const float* __restrict__ E) {
    int w    = (blockIdx.x * blockDim.x + threadIdx.x) >> 5;
    int lane = threadIdx.x & 31;
    if (w >= KCODE + NROWS) return;
    bool isE = (w < KCODE);
    int  r   = isE ? w : (w - KCODE);
    const float4* p = (const float4*)(isE ? (E + (size_t)r * DDIM) : (X + (size_t)r * DDIM));

    float s = 0.f, mx = 1e-20f;
#pragma unroll
    for (int i = 0; i < 4; i++) {
        float4 v = p[lane + 32 * i];
        s += v.x * v.x + v.y * v.y + v.z * v.z + v.w * v.w;
        mx = fmaxf(mx, fmaxf(fmaxf(fabsf(v.x), fabsf(v.y)),
                             fmaxf(fabsf(v.z), fabsf(v.w))));
    }
#pragma unroll
    for (int o = 16; o > 0; o >>= 1) {
        s  += __shfl_xor_sync(0xffffffffu, s, o);
        mx  = fmaxf(mx, __shfl_xor_sync(0xffffffffu, mx, o));
    }
    if (lane == 0) {
        if (isE) g_e2[r] = s;
        else {
            g_x2[r] = s;
            g_rowmin[r] = 0xFFFFFFFFu;
            g_fct[r] = -2.0f * mx / (127.0f * 127.0f * 8192.0f);
        }
    }

    const float scl = isE ? (8192.0f * 127.0f) : (127.0f / mx);
    uint32_t* dst = (isE ? g_Eb8 : g_Xb8) + (size_t)r * (DDIM / 4);
#pragma unroll
    for (int i = 0; i < 4; i++) {
        float4 v = p[lane + 32 * i];
        dst[lane + 32 * i] = s8x4(v.x * scl, v.y * scl, v.z * scl, v.w * scl);
    }
}

// ---------------------------------------------------------------------------
// Kernel 2: s8 IMMA GEMM (128x128 tile, K=512), exact s32 accum.
// Stores fp16 scores AND per-row approximate min (atomicMin on ordered keys).
// Addressing/fragment structure identical to the rel_err==0.0-verified R8.
// ---------------------------------------------------------------------------
__global__ __launch_bounds__(256, 2) void vq_mma_kernel() {
    extern __shared__ char smem[];
    const uint32_t sb = smem_u32(smem);
    const int tid = threadIdx.x;
    const int wid = tid >> 5, lane = tid & 31;
    const int g = lane >> 2, tig = lane & 3;
    const int wm = wid & 3, wn = wid >> 2;          // warp grid 4 x 2
    const int rt = blockIdx.x >> 6;                 // col-tile fastest (L2 reuse)
    const int ct = blockIdx.x & 63;
    const int row0 = rt * TM;
    const int col0 = ct * TN;

    auto stage_cp = [&](int s, int ks) {
#pragma unroll
        for (int i = 0; i < 4; i++) {               // A: 1024 16B chunks
            int u = tid + 256 * i, row = u >> 3, c = u & 7;
            const void* src = g_Xb8 + (size_t)(row0 + row) * (DDIM / 4) + (ks >> 2) + c * 4;
            uint32_t dst = sb + (uint32_t)s * STAGE_BYTES +
                           (uint32_t)(row * 128 + (c ^ (row & 7)) * 16);
            CP_ASYNC16(dst, src);
        }
#pragma unroll
        for (int i = 0; i < 4; i++) {               // B: 1024 16B chunks
            int u = tid + 256 * i, row = u >> 3, c = u & 7;
            const void* src = g_Eb8 + (size_t)(col0 + row) * (DDIM / 4) + (ks >> 2) + c * 4;
            uint32_t dst = sb + B_OFF + (uint32_t)s * STAGE_BYTES +
                           (uint32_t)(row * 128 + (c ^ (row & 7)) * 16);
            CP_ASYNC16(dst, src);
        }
    };

    const int lrow = lane & 7, sel = lane >> 3;
    int arow[2]; const int acb = sel >> 1;
#pragma unroll
    for (int mt = 0; mt < 2; mt++) arow[mt] = wm * 32 + mt * 16 + lrow + (sel & 1) * 8;
    int brow[4]; const int bcb = sel & 1;
#pragma unroll
    for (int ntp = 0; ntp < 4; ntp++) brow[ntp] = wn * 64 + ntp * 16 + (sel >> 1) * 8 + lrow;

    int acc[2][8][4];
#pragma unroll
    for (int mt = 0; mt < 2; mt++)
#pragma unroll
        for (int nt = 0; nt < 8; nt++)
#pragma unroll
            for (int q = 0; q < 4; q++) acc[mt][nt][q] = 0;

    stage_cp(0, 0);  CP_COMMIT();
    stage_cp(1, KB); CP_COMMIT();

    for (int ks = 0; ks < NKS; ks++) {
        CP_WAIT1();
        __syncthreads();
        if (ks < NKS - 2) stage_cp((ks + 2) % NSTAGE, (ks + 2) * KB);
        CP_COMMIT();

        const int buf = ks % NSTAGE;
        const uint32_t As = sb + (uint32_t)buf * STAGE_BYTES;
        const uint32_t Bs = sb + B_OFF + (uint32_t)buf * STAGE_BYTES;

#pragma unroll
        for (int s32 = 0; s32 < 4; s32++) {         // k32 chunk = 16B pair
            uint32_t a[2][4];
#pragma unroll
            for (int mt = 0; mt < 2; mt++) {
                int c = 2 * s32 + acb;
                uint32_t ad = As + arow[mt] * 128 + ((c ^ (arow[mt] & 7)) * 16);
                LDSM_X4(a[mt][0], a[mt][1], a[mt][2], a[mt][3], ad);
            }
            uint32_t b[8][2];
#pragma unroll
            for (int ntp = 0; ntp < 4; ntp++) {
                int c = 2 * s32 + bcb;
                uint32_t bd = Bs + brow[ntp] * 128 + ((c ^ (brow[ntp] & 7)) * 16);
                LDSM_X4(b[2 * ntp][0], b[2 * ntp][1], b[2 * ntp + 1][0], b[2 * ntp + 1][1], bd);
            }
#pragma unroll
            for (int nt = 0; nt < 8; nt++) {
                mma32s8(acc[0][nt], a[0], b[nt]);
                mma32s8(acc[1][nt], a[1], b[nt]);
            }
        }
    }

    // ---- epilogue: score = e2 + dot_int * fct_row -> fp16 store + row min ----
    // (int->float convert exact: |dot_int| < 2^24)
#pragma unroll
    for (int mt = 0; mt < 2; mt++) {
#pragma unroll
        for (int rr = 0; rr < 2; rr++) {
            int row = row0 + wm * 32 + mt * 16 + g + rr * 8;
            const float fct = __ldg(&g_fct[row]);
            __half* srow = g_score + ((size_t)row << 13);
            float rmin = CUDART_INF_F;
#pragma unroll
            for (int nt = 0; nt < 8; nt++) {
                int col = col0 + wn * 64 + nt * 8 + 2 * tig;
                float s0 = fmaf((float)acc[mt][nt][rr * 2],     fct, __ldg(&g_e2[col]));
                float s1 = fmaf((float)acc[mt][nt][rr * 2 + 1], fct, __ldg(&g_e2[col + 1]));
                rmin = fminf(rmin, fminf(s0, s1));
                *(__half2*)(srow + col) = __floats2half2_rn(s0, s1);
            }
            rmin = fminf(rmin, __shfl_xor_sync(0xffffffffu, rmin, 1));
            rmin = fminf(rmin, __shfl_xor_sync(0xffffffffu, rmin, 2));
            if (tig == 0) atomicMin(&g_rowmin[row], fkey(rmin));
        }
    }
}

// ---------------------------------------------------------------------------
// Kernel 3: single-pass rescue + fused gather/STE. One warp per row.
// Margin 1e-3 ~28 sigma of the int8 screen error + ref tie window + half ulp.
// Rescue dist form byte-identical to the rel_err==0.0-proven path.
// ---------------------------------------------------------------------------
__global__ __launch_bounds__(256) void rescue_gather_kernel(
    const float* __restrict__ X, const float* __restrict__ E,
    float* __restrict__ out) {
    int w    = (blockIdx.x * blockDim.x + threadIdx.x) >> 5;
    int lane = threadIdx.x & 31;
    if (w >= NROWS) return;
    const int row = w;
    const uint4* sv = (const uint4*)(g_score + ((size_t)row << 13));
    const float Tf = funkey(g_rowmin[row]) + 1e-3f;

    const float x2v = g_x2[row];
    const float* xr = X + (size_t)row * DDIM;
    unsigned long long best = ~0ull;

    for (int it = 0; it < 32; it++) {
        uint4 v = __ldg(&sv[lane + 32 * it]);
        __half2 h0 = *(__half2*)&v.x, h1 = *(__half2*)&v.y;
        __half2 h2 = *(__half2*)&v.z, h3 = *(__half2*)&v.w;
        __half2 mn2 = __hmin2(__hmin2(h0, h1), __hmin2(h2, h3));
        float mn = fminf(__low2float(mn2), __high2float(mn2));
        if (mn <= Tf) {
            const __half2 hh[4] = {h0, h1, h2, h3};
#pragma unroll
            for (int q = 0; q < 4; q++) {
                float2 f = __half22float2(hh[q]);
                float sc2[2] = {f.x, f.y};
#pragma unroll
                for (int e = 0; e < 2; e++) {
                    if (sc2[e] <= Tf) {
                        int k = (lane + 32 * it) * 8 + q * 2 + e;
                        const float* er = E + (size_t)k * DDIM;
                        float acc = 0.f;
                        for (int d = 0; d < DDIM; d++) acc += xr[d] * er[d];
                        float t    = x2v + g_e2[k];
                        float dist = t - 2.0f * acc;   // exact R1-form dist
                        unsigned long long p =
                            ((unsigned long long)__float_as_uint(dist) << 32) | (unsigned)k;
                        best = (p < best) ? p : best;
                    }
                }
            }
        }
    }
#pragma unroll
    for (int o = 16; o > 0; o >>= 1) {
        unsigned long long q = __shfl_xor_sync(0xffffffffu, best, o);
        best = (q < best) ? q : best;
    }
    const int c = (int)(unsigned)(best & 0xffffffffull);

    // fused gather + STE rounding: out = x + (e - x)
    const float4* ep = (const float4*)(E + (size_t)c * DDIM);
    const float4* xp = (const float4*)xr;
    float4* op = (float4*)(out + (size_t)row * DDIM);
#pragma unroll
    for (int i = 0; i < 4; i++) {
        float4 e = ep[lane + 32 * i];
        float4 x = xp[lane + 32 * i];
        float4 o;
        o.x = __fadd_rn(x.x, __fsub_rn(e.x, x.x));
        o.y = __fadd_rn(x.y, __fsub_rn(e.y, x.y));
        o.z = __fadd_rn(x.z, __fsub_rn(e.z, x.z));
        o.w = __fadd_rn(x.w, __fsub_rn(e.w, x.w));
        op[lane + 32 * i] = o;
    }
}

// ---------------------------------------------------------------------------
extern "C" void kernel_launch(void* const* d_in, const int* in_sizes, int n_in,
                              void* d_out, int out_size) {
    const float* X = (const float*)d_in[0];
    const float* E = (const float*)d_in[1];
    float* out = (float*)d_out;

    cudaFuncSetAttribute(vq_mma_kernel, cudaFuncAttributeMaxDynamicSharedMemorySize,
                         SMEM_BYTES);

    int warps = KCODE + NROWS;
    prep_kernel<<<(warps * 32 + 255) / 256, 256>>>(X, E);
    vq_mma_kernel<<<NRT * NCT, 256, SMEM_BYTES>>>();
    rescue_gather_kernel<<<NROWS / 8, 256>>>(X, E, out);
}

// round 10
// speedup vs baseline: 2.9376x; 1.5225x over previous
#include <cuda_runtime.h>
#include <cuda_bf16.h>
#include <math_constants.h>
#include <cstdint>

// Shapes: latents [16,2048,512] -> [32768,512], embedding [8192,512]
constexpr int DDIM  = 512;
constexpr int KCODE = 8192;
constexpr int NROWS = 16 * 2048;

constexpr int TM = 128;
constexpr int TN = 128;
constexpr int KB = 64;           // bf16 elems per stage row = 128B
constexpr int NSTAGE = 3;
constexpr int NKS = DDIM / KB;   // 8
constexpr int NRT = NROWS / TM;  // 256
constexpr int NCT = KCODE / TN;  // 64

constexpr int   NCAND  = 128;    // per-row candidate slots
constexpr float MARGIN = 1e-3f;  // >= 2*bf16 screen err (5.4e-4) + tie win (1.9e-4)

constexpr uint32_t STAGE_BYTES = TM * KB * 2;               // 16384
constexpr uint32_t B_OFF       = NSTAGE * STAGE_BYTES;      // 49152
constexpr uint32_t SMEM_BYTES  = 2 * NSTAGE * STAGE_BYTES;  // 98304

// ---------------- scratch ----------------
__device__ __nv_bfloat16 g_Xb[NROWS * DDIM];
__device__ __nv_bfloat16 g_Eb[KCODE * DDIM];
__device__ float    g_e2[KCODE];
__device__ float    g_x2[NROWS];
__device__ unsigned g_rowmin[NROWS];            // float-ordered keys
__device__ int      g_cnt[NROWS];               // candidate counters
__device__ int      g_cand[NROWS * NCAND];      // candidate code ids (16 MB)

// ---------------- helpers ----------------
__device__ __forceinline__ uint32_t smem_u32(const void* p) {
    uint32_t a;
    asm("{ .reg .u64 t; cvta.to.shared.u64 t, %1; cvt.u32.u64 %0, t; }" : "=r"(a) : "l"(p));
    return a;
}
__device__ __forceinline__ unsigned fkey(float f) {          // order-preserving
    unsigned b = __float_as_uint(f);
    return b ^ (unsigned)(((int)b >> 31) | 0x80000000);
}
__device__ __forceinline__ float funkey(unsigned k) {
    unsigned b = k ^ (unsigned)((~(int)k >> 31) | 0x80000000);
    return __uint_as_float(b);
}
__device__ __forceinline__ void mma16(float* d, const uint32_t* a, const uint32_t* b) {
    asm volatile(
        "mma.sync.aligned.m16n8k16.row.col.f32.bf16.bf16.f32 "
        "{%0,%1,%2,%3}, {%4,%5,%6,%7}, {%8,%9}, {%0,%1,%2,%3};"
        : "+f"(d[0]), "+f"(d[1]), "+f"(d[2]), "+f"(d[3])
        : "r"(a[0]), "r"(a[1]), "r"(a[2]), "r"(a[3]), "r"(b[0]), "r"(b[1]));
}
#define LDSM_X4(r0, r1, r2, r3, addr)                                            \
    asm volatile("ldmatrix.sync.aligned.m8n8.x4.shared.b16 {%0,%1,%2,%3}, [%4];" \
        : "=r"(r0), "=r"(r1), "=r"(r2), "=r"(r3) : "r"(addr))
#define CP_ASYNC16(dst, src) \
    asm volatile("cp.async.cg.shared.global [%0], [%1], 16;" :: "r"(dst), "l"(src) : "memory")
#define CP_COMMIT()  asm volatile("cp.async.commit_group;" ::: "memory")
#define CP_WAIT1()   asm volatile("cp.async.wait_group 1;" ::: "memory")

// ---------------------------------------------------------------------------
// Kernel 1: norms (R1-proven structure) + bf16 convert + rowmin/cnt init
// ---------------------------------------------------------------------------
__global__ void prep_kernel(const float* __restrict__ X, const float* __restrict__ E) {
    int w    = (blockIdx.x * blockDim.x + threadIdx.x) >> 5;
    int lane = threadIdx.x & 31;
    if (w >= KCODE + NROWS) return;
    bool isE = (w < KCODE);
    int  r   = isE ? w : (w - KCODE);
    const float4* p = (const float4*)(isE ? (E + (size_t)r * DDIM) : (X + (size_t)r * DDIM));

    float s = 0.f;
#pragma unroll
    for (int i = 0; i < 4; i++) {
        float4 v = p[lane + 32 * i];
        s += v.x * v.x + v.y * v.y + v.z * v.z + v.w * v.w;
    }
#pragma unroll
    for (int o = 16; o > 0; o >>= 1) s += __shfl_xor_sync(0xffffffffu, s, o);
    if (lane == 0) {
        if (isE) g_e2[r] = s;
        else { g_x2[r] = s; g_rowmin[r] = 0xFFFFFFFFu; g_cnt[r] = 0; }
    }

    __nv_bfloat162* dst = (__nv_bfloat162*)((isE ? g_Eb : g_Xb) + (size_t)r * DDIM);
#pragma unroll
    for (int i = 0; i < 4; i++) {
        float4 v = p[lane + 32 * i];
        dst[(lane + 32 * i) * 2 + 0] = __floats2bfloat162_rn(v.x, v.y);
        dst[(lane + 32 * i) * 2 + 1] = __floats2bfloat162_rn(v.z, v.w);
    }
}

// ---------------------------------------------------------------------------
// Kernel 2: bf16 GEMM (128x128 tile, K=512) via ldmatrix + mma.sync.
// Epilogue: per-row min -> global atomicMin; append candidate cols within
// MARGIN of the global-so-far min (race-conservative; margin >= 2*err).
// ---------------------------------------------------------------------------
__global__ __launch_bounds__(256, 2) void vq_mma_kernel() {
    extern __shared__ char smem[];
    const uint32_t sb = smem_u32(smem);
    const int tid = threadIdx.x;
    const int wid = tid >> 5, lane = tid & 31;
    const int g = lane >> 2, tig = lane & 3;
    const int wm = wid & 3, wn = wid >> 2;          // warp grid 4 x 2
    const int rt = blockIdx.x >> 6;                 // col-tile fastest (L2 reuse)
    const int ct = blockIdx.x & 63;
    const int row0 = rt * TM;
    const int col0 = ct * TN;

    auto stage_cp = [&](int s, int ks) {
#pragma unroll
        for (int i = 0; i < 4; i++) {               // A: 1024 16B chunks
            int u = tid + 256 * i, row = u >> 3, c = u & 7;
            const void* src = g_Xb + (size_t)(row0 + row) * DDIM + ks + c * 8;
            uint32_t dst = sb + (uint32_t)s * STAGE_BYTES +
                           (uint32_t)(row * 128 + (c ^ (row & 7)) * 16);
            CP_ASYNC16(dst, src);
        }
#pragma unroll
        for (int i = 0; i < 4; i++) {               // B: 1024 16B chunks
            int u = tid + 256 * i, row = u >> 3, c = u & 7;
            const void* src = g_Eb + (size_t)(col0 + row) * DDIM + ks + c * 8;
            uint32_t dst = sb + B_OFF + (uint32_t)s * STAGE_BYTES +
                           (uint32_t)(row * 128 + (c ^ (row & 7)) * 16);
            CP_ASYNC16(dst, src);
        }
    };

    const int lrow = lane & 7, sel = lane >> 3;
    int arow[2]; const int acb = sel >> 1;
#pragma unroll
    for (int mt = 0; mt < 2; mt++) arow[mt] = wm * 32 + mt * 16 + lrow + (sel & 1) * 8;
    int brow[4]; const int bcb = sel & 1;
#pragma unroll
    for (int ntp = 0; ntp < 4; ntp++) brow[ntp] = wn * 64 + ntp * 16 + (sel >> 1) * 8 + lrow;

    float acc[2][8][4];
#pragma unroll
    for (int mt = 0; mt < 2; mt++)
#pragma unroll
        for (int nt = 0; nt < 8; nt++)
#pragma unroll
            for (int q = 0; q < 4; q++) acc[mt][nt][q] = 0.f;

    stage_cp(0, 0);  CP_COMMIT();
    stage_cp(1, KB); CP_COMMIT();

    for (int ks = 0; ks < NKS; ks++) {
        CP_WAIT1();
        __syncthreads();
        if (ks < NKS - 2) stage_cp((ks + 2) % NSTAGE, (ks + 2) * KB);
        CP_COMMIT();

        const int buf = ks % NSTAGE;
        const uint32_t As = sb + (uint32_t)buf * STAGE_BYTES;
        const uint32_t Bs = sb + B_OFF + (uint32_t)buf * STAGE_BYTES;

#pragma unroll
        for (int s16 = 0; s16 < 4; s16++) {
            uint32_t a[2][4];
#pragma unroll
            for (int mt = 0; mt < 2; mt++) {
                int c = 2 * s16 + acb;
                uint32_t ad = As + arow[mt] * 128 + ((c ^ (arow[mt] & 7)) * 16);
                LDSM_X4(a[mt][0], a[mt][1], a[mt][2], a[mt][3], ad);
            }
            uint32_t b[8][2];
#pragma unroll
            for (int ntp = 0; ntp < 4; ntp++) {
                int c = 2 * s16 + bcb;
                uint32_t bd = Bs + brow[ntp] * 128 + ((c ^ (brow[ntp] & 7)) * 16);
                LDSM_X4(b[2 * ntp][0], b[2 * ntp][1], b[2 * ntp + 1][0], b[2 * ntp + 1][1], bd);
            }
#pragma unroll
            for (int nt = 0; nt < 8; nt++) {
                mma16(acc[0][nt], a[0], b[nt]);
                mma16(acc[1][nt], a[1], b[nt]);
            }
        }
    }

    // ---- epilogue: per-row min + candidate append (no score matrix) ----
#pragma unroll
    for (int mt = 0; mt < 2; mt++) {
#pragma unroll
        for (int rr = 0; rr < 2; rr++) {
            const int row = row0 + wm * 32 + mt * 16 + g + rr * 8;
            float s0[8], s1[8];
            float rmin = CUDART_INF_F;
#pragma unroll
            for (int nt = 0; nt < 8; nt++) {
                int col = col0 + wn * 64 + nt * 8 + 2 * tig;
                s0[nt] = __ldg(&g_e2[col])     - 2.0f * acc[mt][nt][rr * 2];
                s1[nt] = __ldg(&g_e2[col + 1]) - 2.0f * acc[mt][nt][rr * 2 + 1];
                rmin = fminf(rmin, fminf(s0[nt], s1[nt]));
            }
            rmin = fminf(rmin, __shfl_xor_sync(0xffffffffu, rmin, 1));
            rmin = fminf(rmin, __shfl_xor_sync(0xffffffffu, rmin, 2));
            unsigned mykey = fkey(rmin);
            unsigned oldkey = 0xFFFFFFFFu;
            if (tig == 0) oldkey = atomicMin(&g_rowmin[row], mykey);
            oldkey = __shfl_sync(0xffffffffu, oldkey, lane & ~3);
            const float Tf = funkey(min(oldkey, mykey)) + MARGIN;
#pragma unroll
            for (int nt = 0; nt < 8; nt++) {
                int col = col0 + wn * 64 + nt * 8 + 2 * tig;
                if (s0[nt] <= Tf) {
                    int idx = atomicAdd(&g_cnt[row], 1);
                    if (idx < NCAND) g_cand[row * NCAND + idx] = col;
                }
                if (s1[nt] <= Tf) {
                    int idx = atomicAdd(&g_cnt[row], 1);
                    if (idx < NCAND) g_cand[row * NCAND + idx] = col + 1;
                }
            }
        }
    }
}

// ---------------------------------------------------------------------------
// Kernel 3: candidate rescue + fused gather/STE. One warp per row.
// Exact dist form byte-identical to the rel_err==0.0-proven path.
// Overflow (>NCAND candidates) falls back to an exact full-row scan.
// ---------------------------------------------------------------------------
__global__ __launch_bounds__(256) void rescue_gather_kernel(
    const float* __restrict__ X, const float* __restrict__ E,
    float* __restrict__ out) {
    int w    = (blockIdx.x * blockDim.x + threadIdx.x) >> 5;
    int lane = threadIdx.x & 31;
    if (w >= NROWS) return;
    const int row = w;
    const int cnt = g_cnt[row];
    const float x2v = g_x2[row];
    const float* xr = X + (size_t)row * DDIM;
    unsigned long long best = ~0ull;

    if (cnt > NCAND) {
        // overflow fallback: exact scan of all codes (correct, ~never taken)
        for (int k = lane; k < KCODE; k += 32) {
            const float* er = E + (size_t)k * DDIM;
            float acc = 0.f;
            for (int d = 0; d < DDIM; d++) acc += xr[d] * er[d];
            float t    = x2v + g_e2[k];
            float dist = t - 2.0f * acc;
            unsigned long long p =
                ((unsigned long long)__float_as_uint(dist) << 32) | (unsigned)k;
            best = (p < best) ? p : best;
        }
    } else {
        for (int i = lane; i < cnt; i += 32) {
            int k = g_cand[row * NCAND + i];
            const float* er = E + (size_t)k * DDIM;
            float acc = 0.f;
            for (int d = 0; d < DDIM; d++) acc += xr[d] * er[d];
            float t    = x2v + g_e2[k];
            float dist = t - 2.0f * acc;       // exact R1-form dist
            unsigned long long p =
                ((unsigned long long)__float_as_uint(dist) << 32) | (unsigned)k;
            best = (p < best) ? p : best;
        }
    }
#pragma unroll
    for (int o = 16; o > 0; o >>= 1) {
        unsigned long long q = __shfl_xor_sync(0xffffffffu, best, o);
        best = (q < best) ? q : best;
    }
    const int c = (int)(unsigned)(best & 0xffffffffull);

    // fused gather + STE rounding: out = x + (e - x)
    const float4* ep = (const float4*)(E + (size_t)c * DDIM);
    const float4* xp = (const float4*)xr;
    float4* op = (float4*)(out + (size_t)row * DDIM);
#pragma unroll
    for (int i = 0; i < 4; i++) {
        float4 e = ep[lane + 32 * i];
        float4 x = xp[lane + 32 * i];
        float4 o;
        o.x = __fadd_rn(x.x, __fsub_rn(e.x, x.x));
        o.y = __fadd_rn(x.y, __fsub_rn(e.y, x.y));
        o.z = __fadd_rn(x.z, __fsub_rn(e.z, x.z));
        o.w = __fadd_rn(x.w, __fsub_rn(e.w, x.w));
        op[lane + 32 * i] = o;
    }
}

// ---------------------------------------------------------------------------
extern "C" void kernel_launch(void* const* d_in, const int* in_sizes, int n_in,
                              void* d_out, int out_size) {
    const float* X = (const float*)d_in[0];
    const float* E = (const float*)d_in[1];
    float* out = (float*)d_out;

    cudaFuncSetAttribute(vq_mma_kernel, cudaFuncAttributeMaxDynamicSharedMemorySize,
                         SMEM_BYTES);

    int warps = KCODE + NROWS;
    prep_kernel<<<(warps * 32 + 255) / 256, 256>>>(X, E);
    vq_mma_kernel<<<NRT * NCT, 256, SMEM_BYTES>>>();
    rescue_gather_kernel<<<NROWS / 8, 256>>>(X, E, out);
}